// round 13
// baseline (speedup 1.0000x reference)
#include <cuda_runtime.h>

#define NEG_INF __int_as_float(0xff800000)

typedef unsigned long long ull;

#define RS 34          // float2 per smem img row
#define CS2 340        // float2 per c2 tile: 10 rows x 34

// packed f32x2 add + unpack halves (unpack = register aliasing, free in SASS)
#define ADDU(LO, HI, V, K)                                                  \
    asm("{\n\t.reg .b64 t;\n\tadd.rn.f32x2 t, %2, %3;\n\tmov.b64 {%0,%1}, t;\n\t}" \
        : "=f"(LO), "=f"(HI) : "l"(V), "l"(K))

// Exact fp32 max-plus conv; f32x2 packed adds; 4-row y-block; 2-way c-split;
// FULLY UNROLLED c2 loop (one load bubble total, cross-iteration pipelining).
// Block: 128 threads = 2 ch-halves x (16 xl x 2 og x 2 typ).
// Thread: 1 o x 2 x x 4 y over 8 of 16 c2 (8 outputs); halves combined via smem.
// Grid: (o-pair=16, ytile=4, b=8) = 512 blocks x 4 warps = 2048 warps.
__global__ __launch_bounds__(128)
void bconv_kernel(const float* __restrict__ img,
                  const float* __restrict__ ker,
                  float* __restrict__ out)
{
    __shared__ __align__(16) float2 simg[16 * CS2];    // 43520 B (reused for combine)
    __shared__ __align__(16) float2 sker[16 * 2 * 10]; //  2560 B

    const int o2   = blockIdx.x;         // 0..15
    const int yt   = blockIdx.y;         // 0..3
    const int b    = blockIdx.z;         // 0..7
    const int tid  = threadIdx.x;
    const int ch   = tid >> 6;           // c-half: 0 or 1
    const int tidL = tid & 63;
    const int xl   = tidL & 15;          // x0 = 2*xl
    const int og   = (tidL >> 4) & 1;    // which o of the pair
    const int typ  = tidL >> 5;          // 0..1 (4-row y group)
    const int y0   = yt * 8;

    const float2 ninf2 = make_float2(NEG_INF, NEG_INF);

    // ---- halo columns xx=0,33 (w=-1,32): always -inf. 320 entries ----
#pragma unroll
    for (int it = 0; it < 3; it++) {
        int t = tid + it * 128;
        if (t < 320) {
            int c2  = t / 20;
            int rem = t - c2 * 20;
            simg[c2 * CS2 + (rem >> 1) * RS + ((rem & 1) ? 33 : 0)] = ninf2;
        }
    }

    // ---- interior: 1280 float4-tasks: c2(16) x rr(10) x q(8) ----
    const float* gimg = img + b * 32768;
#pragma unroll
    for (int it = 0; it < 10; it++) {
        int t   = tid + it * 128;
        int c2  = t / 80;
        int rem = t - c2 * 80;
        int rr  = rem >> 3;
        int q   = rem & 7;
        int h   = y0 - 1 + rr;
        float2* sp = simg + c2 * CS2 + rr * RS + 1 + q * 4;
        if ((unsigned)h < 32u) {
            const float4 a  = *(const float4*)(gimg + (c2 * 2)     * 1024 + h * 32 + q * 4);
            const float4 bb = *(const float4*)(gimg + (c2 * 2 + 1) * 1024 + h * 32 + q * 4);
            sp[0] = make_float2(a.x, bb.x);
            sp[1] = make_float2(a.y, bb.y);
            sp[2] = make_float2(a.z, bb.z);
            sp[3] = make_float2(a.w, bb.w);
        } else {
            sp[0] = ninf2; sp[1] = ninf2; sp[2] = ninf2; sp[3] = ninf2;
        }
    }

    // ---- kernel slice: 288 entries: c2(16) x og(2) x p(9) ----
#pragma unroll
    for (int it = 0; it < 3; it++) {
        int t = tid + it * 128;
        if (t < 288) {
            int c2  = t / 18;
            int rem = t - c2 * 18;
            int g   = rem / 9;
            int p   = rem - g * 9;
            int dy  = p / 3, dx = p - dy * 3;
            const float* kb = ker + (2 - dy) * 3 + (2 - dx);
            int o = o2 * 2 + g, c0 = c2 * 2;
            sker[(c2 * 2 + g) * 10 + p] =
                make_float2(kb[(o * 32 + c0) * 9], kb[(o * 32 + c0 + 1) * 9]);
        }
    }
    __syncthreads();

    // 16 chains: a[cpar*8 + yy*2 + xi]
    float a[16];
#pragma unroll
    for (int i = 0; i < 16; i++) a[i] = NEG_INF;

    const float2* vb  = simg + (typ * 4) * RS + 2 * xl;   // rows typ*4 .. typ*4+5
    const float2* kb2 = sker + og * 10 + ch * 8 * 20;     // this half's first c2

#pragma unroll
    for (int i = 0; i < 8; i++) {
        // k: 9 packed (c0,c1) pairs, 2 distinct addrs per warp (broadcast)
        const ulonglong2* kp = (const ulonglong2*)(kb2 + i * 20);
        ulonglong2 q0 = kp[0], q1 = kp[1], q2 = kp[2], q3 = kp[3];
        ull k8 = *(const ull*)(kb2 + i * 20 + 8);
        ull k[9];
        k[0] = q0.x; k[1] = q0.y; k[2] = q1.x; k[3] = q1.y;
        k[4] = q2.x; k[5] = q2.y; k[6] = q3.x; k[7] = q3.y; k[8] = k8;

        // v: 6 rows x 4 packed channel-pairs (og halves share addrs -> dedup)
        const float2* vp = vb + (ch * 8 + i) * CS2;
        ull w[6][4];
#pragma unroll
        for (int r = 0; r < 6; r++) {
            ulonglong2 A = *(const ulonglong2*)(vp + r * RS);
            ulonglong2 B = *(const ulonglong2*)(vp + r * RS + 2);
            w[r][0] = A.x; w[r][1] = A.y; w[r][2] = B.x; w[r][3] = B.y;
        }

        // yy-major: row yy+dy first consumed late -> natural pipelining room
#pragma unroll
        for (int yy = 0; yy < 4; yy++) {
#pragma unroll
            for (int p = 0; p < 9; p++) {
                const int dy = p / 3, dx = p - dy * 3;
                const ull kk = k[p];
                float lo0, hi0, lo1, hi1;
                ADDU(lo0, hi0, w[dy + yy][dx],     kk);   // output x0
                ADDU(lo1, hi1, w[dy + yy][dx + 1], kk);   // output x0+1
                a[yy * 2 + 0]     = fmaxf(a[yy * 2 + 0],     lo0);
                a[8 + yy * 2 + 0] = fmaxf(a[8 + yy * 2 + 0], hi0);
                a[yy * 2 + 1]     = fmaxf(a[yy * 2 + 1],     lo1);
                a[8 + yy * 2 + 1] = fmaxf(a[8 + yy * 2 + 1], hi1);
            }
        }
    }

    // ---- fold c-parity chains -> r[yy][xi] (8 outputs) ----
    float r[8];
#pragma unroll
    for (int i = 0; i < 8; i++) r[i] = fmaxf(a[i], a[8 + i]);

    // ---- combine the two c-halves through smem (overlay on simg) ----
    __syncthreads();                       // all simg reads done
    float4* scomb = (float4*)simg;
    if (ch == 1) {
        scomb[tidL * 2 + 0] = make_float4(r[0], r[1], r[2], r[3]);
        scomb[tidL * 2 + 1] = make_float4(r[4], r[5], r[6], r[7]);
    }
    __syncthreads();
    if (ch == 0) {
        float4 p0 = scomb[tidL * 2 + 0];
        float4 p1 = scomb[tidL * 2 + 1];
        r[0] = fmaxf(r[0], p0.x); r[1] = fmaxf(r[1], p0.y);
        r[2] = fmaxf(r[2], p0.z); r[3] = fmaxf(r[3], p0.w);
        r[4] = fmaxf(r[4], p1.x); r[5] = fmaxf(r[5], p1.y);
        r[6] = fmaxf(r[6], p1.z); r[7] = fmaxf(r[7], p1.w);

        const int o  = o2 * 2 + og;
        const int yb = y0 + typ * 4;
        float2* gout = (float2*)(out + ((b * 32 + o) * 32 + yb) * 32 + 2 * xl);
#pragma unroll
        for (int yy = 0; yy < 4; yy++)
            gout[yy * 16] = make_float2(r[yy * 2], r[yy * 2 + 1]);   // +32 floats per row
    }
}

extern "C" void kernel_launch(void* const* d_in, const int* in_sizes, int n_in,
                              void* d_out, int out_size)
{
    const float* img = (const float*)d_in[0];
    const float* ker = (const float*)d_in[1];
    float*       out = (float*)d_out;
    dim3 grid(16, 4, 8);   // (o-pair, ytile, batch)
    bconv_kernel<<<grid, 128>>>(img, ker, out);
}

// round 14
// speedup vs baseline: 1.1940x; 1.1940x over previous
#include <cuda_runtime.h>

#define NEG_INF __int_as_float(0xff800000)

typedef unsigned long long ull;

#define RS 34          // float2 per smem img row
#define CS2 340        // float2 per c2 tile: 10 rows x 34

// packed f32x2 add + unpack halves
#define ADDU(LO, HI, V, K)                                                  \
    asm("{\n\t.reg .b64 t;\n\tadd.rn.f32x2 t, %2, %3;\n\tmov.b64 {%0,%1}, t;\n\t}" \
        : "=f"(LO), "=f"(HI) : "l"(V), "l"(K))

// Exact fp32 max-plus conv; f32x2 adds; 4-row y-block; 2-way c-split; full unroll;
// 2 o-pairs per block (prologue amortized over 4 output channels).
// Block: 256 threads = 2 ch x (2 typ x 2 o2l x 2 og x 16 xl).
// Thread: 1 o x 2 x x 4 y over 8 of 16 c2 (8 outputs); halves combined via smem.
// Grid: (o-quad=8, ytile=4, b=8) = 256 blocks x 8 warps = 2048 warps.
__global__ __launch_bounds__(256)
void bconv_kernel(const float* __restrict__ img,
                  const float* __restrict__ ker,
                  float* __restrict__ out)
{
    __shared__ __align__(16) float2 simg[16 * CS2];       // 43520 B (reused for combine)
    __shared__ __align__(16) float2 sker[16 * 4 * 10];    //  5120 B

    const int oq   = blockIdx.x;         // 0..7 (group of 4 o-channels)
    const int yt   = blockIdx.y;         // 0..3
    const int b    = blockIdx.z;         // 0..7
    const int tid  = threadIdx.x;
    const int ch   = tid >> 7;           // c-half: 0 or 1
    const int tidL = tid & 127;
    const int xl   = tidL & 15;          // x0 = 2*xl
    const int og   = (tidL >> 4) & 1;    // o within pair
    const int o2l  = (tidL >> 5) & 1;    // which o-pair of the block
    const int typ  = (tidL >> 6) & 1;    // 4-row y group
    const int y0   = yt * 8;

    const float2 ninf2 = make_float2(NEG_INF, NEG_INF);

    // ---- halo columns xx=0,33 (w=-1,32): always -inf. 320 entries ----
#pragma unroll
    for (int it = 0; it < 2; it++) {
        int t = tid + it * 256;
        if (t < 320) {
            int c2  = t / 20;
            int rem = t - c2 * 20;
            simg[c2 * CS2 + (rem >> 1) * RS + ((rem & 1) ? 33 : 0)] = ninf2;
        }
    }

    // ---- interior: 1280 float4-tasks: c2(16) x rr(10) x q(8) ----
    const float* gimg = img + b * 32768;
#pragma unroll
    for (int it = 0; it < 5; it++) {
        int t   = tid + it * 256;
        int c2  = t / 80;
        int rem = t - c2 * 80;
        int rr  = rem >> 3;
        int q   = rem & 7;
        int h   = y0 - 1 + rr;
        float2* sp = simg + c2 * CS2 + rr * RS + 1 + q * 4;
        if ((unsigned)h < 32u) {
            const float4 a  = *(const float4*)(gimg + (c2 * 2)     * 1024 + h * 32 + q * 4);
            const float4 bb = *(const float4*)(gimg + (c2 * 2 + 1) * 1024 + h * 32 + q * 4);
            sp[0] = make_float2(a.x, bb.x);
            sp[1] = make_float2(a.y, bb.y);
            sp[2] = make_float2(a.z, bb.z);
            sp[3] = make_float2(a.w, bb.w);
        } else {
            sp[0] = ninf2; sp[1] = ninf2; sp[2] = ninf2; sp[3] = ninf2;
        }
    }

    // ---- kernel slice: 576 entries: c2(16) x o2l(2) x og(2) x p(9) ----
#pragma unroll
    for (int it = 0; it < 3; it++) {
        int t = tid + it * 256;
        if (t < 576) {
            int c2  = t / 36;
            int rem = t - c2 * 36;
            int ol  = rem / 18;
            int g   = (rem / 9) & 1;
            int p   = rem - ol * 18 - g * 9;
            int dy  = p / 3, dx = p - dy * 3;
            const float* kb = ker + (2 - dy) * 3 + (2 - dx);
            int o  = (oq * 2 + ol) * 2 + g;
            int c0 = c2 * 2;
            sker[((c2 * 2 + ol) * 2 + g) * 10 + p] =
                make_float2(kb[(o * 32 + c0) * 9], kb[(o * 32 + c0 + 1) * 9]);
        }
    }
    __syncthreads();

    // 16 chains: a[cpar*8 + yy*2 + xi]
    float a[16];
#pragma unroll
    for (int i = 0; i < 16; i++) a[i] = NEG_INF;

    const float2* vb  = simg + (typ * 4) * RS + 2 * xl;          // rows typ*4 .. typ*4+5
    const float2* kb2 = sker + (o2l * 2 + og) * 10 + ch * 8 * 40; // this thread's k base

#pragma unroll
    for (int i = 0; i < 8; i++) {
        // k: 9 packed (c0,c1) pairs; 4 distinct addrs per warp (64B -> 1 wf)
        const ulonglong2* kp = (const ulonglong2*)(kb2 + i * 40);
        ulonglong2 q0 = kp[0], q1 = kp[1], q2 = kp[2], q3 = kp[3];
        ull k8 = *(const ull*)(kb2 + i * 40 + 8);
        ull k[9];
        k[0] = q0.x; k[1] = q0.y; k[2] = q1.x; k[3] = q1.y;
        k[4] = q2.x; k[5] = q2.y; k[6] = q3.x; k[7] = q3.y; k[8] = k8;

        // v: 6 rows x 4 packed channel-pairs (o-threads share addrs -> dedup)
        const float2* vp = vb + (ch * 8 + i) * CS2;
        ull w[6][4];
#pragma unroll
        for (int r = 0; r < 6; r++) {
            ulonglong2 A = *(const ulonglong2*)(vp + r * RS);
            ulonglong2 B = *(const ulonglong2*)(vp + r * RS + 2);
            w[r][0] = A.x; w[r][1] = A.y; w[r][2] = B.x; w[r][3] = B.y;
        }

#pragma unroll
        for (int yy = 0; yy < 4; yy++) {
#pragma unroll
            for (int p = 0; p < 9; p++) {
                const int dy = p / 3, dx = p - dy * 3;
                const ull kk = k[p];
                float lo0, hi0, lo1, hi1;
                ADDU(lo0, hi0, w[dy + yy][dx],     kk);
                ADDU(lo1, hi1, w[dy + yy][dx + 1], kk);
                a[yy * 2 + 0]     = fmaxf(a[yy * 2 + 0],     lo0);
                a[8 + yy * 2 + 0] = fmaxf(a[8 + yy * 2 + 0], hi0);
                a[yy * 2 + 1]     = fmaxf(a[yy * 2 + 1],     lo1);
                a[8 + yy * 2 + 1] = fmaxf(a[8 + yy * 2 + 1], hi1);
            }
        }
    }

    // ---- fold c-parity chains -> r[yy][xi] (8 outputs) ----
    float r[8];
#pragma unroll
    for (int i = 0; i < 8; i++) r[i] = fmaxf(a[i], a[8 + i]);

    // ---- combine the two c-halves through smem (overlay on simg) ----
    __syncthreads();                       // all simg reads done
    float4* scomb = (float4*)simg;
    if (ch == 1) {
        scomb[tidL * 2 + 0] = make_float4(r[0], r[1], r[2], r[3]);
        scomb[tidL * 2 + 1] = make_float4(r[4], r[5], r[6], r[7]);
    }
    __syncthreads();
    if (ch == 0) {
        float4 p0 = scomb[tidL * 2 + 0];
        float4 p1 = scomb[tidL * 2 + 1];
        r[0] = fmaxf(r[0], p0.x); r[1] = fmaxf(r[1], p0.y);
        r[2] = fmaxf(r[2], p0.z); r[3] = fmaxf(r[3], p0.w);
        r[4] = fmaxf(r[4], p1.x); r[5] = fmaxf(r[5], p1.y);
        r[6] = fmaxf(r[6], p1.z); r[7] = fmaxf(r[7], p1.w);

        const int o  = (oq * 2 + o2l) * 2 + og;
        const int yb = y0 + typ * 4;
        float2* gout = (float2*)(out + ((b * 32 + o) * 32 + yb) * 32 + 2 * xl);
#pragma unroll
        for (int yy = 0; yy < 4; yy++)
            gout[yy * 16] = make_float2(r[yy * 2], r[yy * 2 + 1]);
    }
}

extern "C" void kernel_launch(void* const* d_in, const int* in_sizes, int n_in,
                              void* d_out, int out_size)
{
    const float* img = (const float*)d_in[0];
    const float* ker = (const float*)d_in[1];
    float*       out = (float*)d_out;
    dim3 grid(8, 4, 8);   // (o-quad, ytile, batch)
    bconv_kernel<<<grid, 256>>>(img, ker, out);
}